// round 16
// baseline (speedup 1.0000x reference)
#include <cuda_runtime.h>
#include <cstdint>

#define HH 400
#define WW 400
#define CC 128
#define KS 25
#define NPIX (HH*WW)
#define PW 424                  // padded row stride (12 + 400 + 12)
#define PROW (HH*PW)            // floats per channel plane (400*424)

// ---------------- device scratch ----------------
__device__ float g_cubeP[(size_t)CC * PROW + 4096];   // [c][row][424], cols 0..11 / 412..423 stay zero
__device__ float g_normP[PROW + 4096];                // padded norms, pads stay zero
__device__ float g_sad[(size_t)325 * NPIX];           // sad planes [ (di-12)*25+dj ][ row*400+col ]
__device__ float g_gx[NPIX + 16];                     // phase-A partial gx
__device__ float g_gy[NPIX + 16];                     // phase-A partial gy
__device__ unsigned int g_max_u;

// ---------------- helpers ----------------
__device__ __forceinline__ float kweight(int i, int j) {
    int ii = min(i, 24 - i);
    if (j < 12) return (float)(j - 12 - ii);
    if (j > 12) return (float)(j - 12 + ii);
    return 0.0f;
}
__device__ __forceinline__ float acos_poly(float x) {
    float ax = fabsf(x);
    float p = fmaf(ax, -0.0012624911f, 0.0066700901f);
    p = fmaf(p, ax, -0.0170881256f);
    p = fmaf(p, ax,  0.0308918810f);
    p = fmaf(p, ax, -0.0501743046f);
    p = fmaf(p, ax,  0.0889789874f);
    p = fmaf(p, ax, -0.2145988016f);
    p = fmaf(p, ax,  1.5707963050f);
    float om = 1.0f - ax;
    float s;
    asm("sqrt.approx.f32 %0, %1;" : "=f"(s) : "f"(om));
    float t = s * p;
    return (x < 0.0f) ? (3.14159265358979f - t) : t;
}

// ---------------- K1: transpose pixel-major -> padded channel-major ----------------
__global__ void k_transpose(const float* __restrict__ cube) {
    __shared__ float tile[32][CC + 4];
    int px0 = blockIdx.x * 32;
    int t = threadIdx.x;                 // 256 threads
    {
        int lp = t >> 3;
        int cbk = (t & 7) << 4;
        const float4* src = reinterpret_cast<const float4*>(cube + (size_t)(px0 + lp) * CC + cbk);
        #pragma unroll
        for (int q = 0; q < 4; q++) {
            float4 v = src[q];
            tile[lp][cbk + 4*q + 0] = v.x;
            tile[lp][cbk + 4*q + 1] = v.y;
            tile[lp][cbk + 4*q + 2] = v.z;
            tile[lp][cbk + 4*q + 3] = v.w;
        }
    }
    __syncthreads();
    int lane = t & 31;
    int crow = t >> 5;
    int px = px0 + lane;
    int row = px / WW;
    int col = px - row * WW;
    size_t dst = (size_t)row * PW + 12 + col;
    #pragma unroll
    for (int it = 0; it < 16; it++) {
        int c = it * 8 + crow;
        g_cubeP[(size_t)c * PROW + dst] = tile[lane][c];
    }
    if (blockIdx.x == 0 && t == 0) g_max_u = 0u;
}

// ---------------- K2: per-pixel norms (warp per pixel, reads original cube) ----------------
__global__ void k_norm(const float* __restrict__ cube) {
    int px = blockIdx.x * 8 + (threadIdx.x >> 5);
    int l = threadIdx.x & 31;
    if (px >= NPIX) return;
    const float* p = cube + (size_t)px * CC;
    float s = 0.0f;
    #pragma unroll
    for (int i = 0; i < 4; i++) { float v = p[l + 32*i]; s = fmaf(v, v, s); }
    #pragma unroll
    for (int o = 16; o; o >>= 1) s += __shfl_xor_sync(0xffffffffu, s, o);
    if (l == 0) {
        int row = px / WW;
        int col = px - row * WW;
        g_normP[(size_t)row * PW + 12 + col] = sqrtf(s);
    }
}

// ---------------- K3: Phase A — lower-half pairs: dots, sad planes, own partials ----------------
// grid (4, 49), 256 thr; warp = center row (0..391, active <=387), lane = 4 cols.
__global__ void __launch_bounds__(256, 1) k_phaseA() {
    __shared__ float wkx[13*25], wky[13*25];
    int t = threadIdx.x;
    for (int i = t; i < 325; i += 256) {
        int di = 12 + i / 25, dj = i % 25;
        bool on = !(di == 12 && dj <= 12);     // lower set only (di=12: dj>=13)
        wkx[i] = on ? kweight(di, dj) : 0.0f;
        wky[i] = on ? kweight(dj, di) : 0.0f;
    }
    __syncthreads();

    const int w = t >> 5;
    const int L = t & 31;
    const int r = blockIdx.y * 8 + w;               // center row
    const int x = blockIdx.x * 128 + 4 * L;         // center col base (real coords)
    if (r > 387) return;                            // whole-warp mask
    const bool cvalid = (x < WW);                   // x multiple of 4 -> x<=396 -> x+3<=399

    const float* ctr = g_cubeP + (size_t)r * PW + 12 + x;     // center (padded col = 12+x)
    float ncv[4];
    {
        float4 n4 = *reinterpret_cast<const float4*>(g_normP + (size_t)r * PW + 12 + x);
        ncv[0] = n4.x; ncv[1] = n4.y; ncv[2] = n4.z; ncv[3] = n4.w;
    }
    float gx[4] = {0,0,0,0};
    float gy[4] = {0,0,0,0};

    #pragma unroll 1
    for (int di = 12; di < KS; di++) {
        int srow = r + di - 12;                               // <= 399
        const float* bs = g_cubeP + (size_t)srow * PW + x;    // window: s[j] = pixel col x+j-12 (padded)

        float acc[4][KS];
        #pragma unroll
        for (int p = 0; p < 4; p++)
            #pragma unroll
            for (int dj = 0; dj < KS; dj++) acc[p][dj] = 0.0f;

        #pragma unroll 2
        for (int c = 0; c < CC; c++) {
            size_t coff = (size_t)c * PROW;
            float4 ct4 = *reinterpret_cast<const float4*>(ctr + coff);
            float ctv[4] = {ct4.x, ct4.y, ct4.z, ct4.w};
            float s[28];
            #pragma unroll
            for (int j = 0; j < 7; j++) {
                float4 v = *reinterpret_cast<const float4*>(bs + coff + 4*j);
                s[4*j + 0] = v.x; s[4*j + 1] = v.y; s[4*j + 2] = v.z; s[4*j + 3] = v.w;
            }
            #pragma unroll
            for (int p = 0; p < 4; p++)
                #pragma unroll
                for (int dj = 0; dj < KS; dj++)
                    acc[p][dj] = fmaf(ctv[p], s[p + dj], acc[p][dj]);
        }

        // epilogue: sad -> plane store + own weighted partials
        const float* nrow = g_normP + (size_t)srow * PW + x;
        float ns[28];
        #pragma unroll
        for (int j = 0; j < 7; j++) {
            float4 v = *reinterpret_cast<const float4*>(nrow + 4*j);
            ns[4*j + 0] = v.x; ns[4*j + 1] = v.y; ns[4*j + 2] = v.z; ns[4*j + 3] = v.w;
        }
        int mdi = di - 12;
        #pragma unroll
        for (int dj = 0; dj < KS; dj++) {
            float kxv = wkx[mdi*25 + dj];
            float kyv = wky[mdi*25 + dj];
            float sad4[4];
            #pragma unroll
            for (int p = 0; p < 4; p++) {
                float den = fmaf(ncv[p], ns[p + dj], 1e-4f);
                float ratio = __fdividef(acc[p][dj], den);
                ratio = fminf(fmaxf(ratio, -1.0f + 1e-6f), 1.0f - 1e-6f);
                float sad = acos_poly(ratio);
                sad4[p] = sad;
                gx[p] = fmaf(sad, kxv, gx[p]);
                gy[p] = fmaf(sad, kyv, gy[p]);
            }
            if (cvalid) {
                float4* dst = reinterpret_cast<float4*>(
                    g_sad + (size_t)(mdi*25 + dj) * NPIX + (size_t)r * WW + x);
                *dst = make_float4(sad4[0], sad4[1], sad4[2], sad4[3]);
            }
        }
    }

    if (cvalid) {
        size_t o = (size_t)r * WW + x;
        *reinterpret_cast<float4*>(g_gx + o) = make_float4(gx[0], gx[1], gx[2], gx[3]);
        *reinterpret_cast<float4*>(g_gy + o) = make_float4(gy[0], gy[1], gy[2], gy[3]);
    }
}

// ---------------- K4: Phase B — gather mirrored upper-half, finalize edge ----------------
// grid (3, 47), 256 thr; warp = interior row (12..387), lane = 4 cols (12..387).
__global__ void __launch_bounds__(256, 1) k_phaseB(float* __restrict__ out) {
    __shared__ float wkx[13*25], wky[13*25];
    __shared__ unsigned int blkmax;
    int t = threadIdx.x;
    if (t == 0) blkmax = 0u;
    for (int i = t; i < 325; i += 256) {
        int di = 12 + i / 25, dj = i % 25;
        wkx[i] = kweight(di, dj);
        wky[i] = kweight(dj, di);
    }
    __syncthreads();

    const int w = t >> 5;
    const int L = t & 31;
    const int r = 12 + blockIdx.y * 8 + w;          // 12..387
    const int x = 12 + blockIdx.x * 128 + 4 * L;    // 12..392
    const bool valid = (x + 3) <= 387;

    float gx[4], gy[4];
    {
        size_t o = (size_t)r * WW + x;
        float4 px4 = *reinterpret_cast<const float4*>(g_gx + o);
        float4 py4 = *reinterpret_cast<const float4*>(g_gy + o);
        gx[0]=px4.x; gx[1]=px4.y; gx[2]=px4.z; gx[3]=px4.w;
        gy[0]=py4.x; gy[1]=py4.y; gy[2]=py4.z; gy[3]=py4.w;
    }

    // upper pairs via mirror: for m=(di,dj) lower, contribution -sad_m[p - mvec] * k[m]
    #pragma unroll 1
    for (int mdi = 0; mdi < 13; mdi++) {
        int qrow = r - mdi;                          // r - (di-12) >= 0
        const float* plbase = g_sad + (size_t)qrow * WW + (x + 12);
        int dj0 = (mdi == 0) ? 13 : 0;               // di=12: only dj>=13 in lower set
        #pragma unroll 5
        for (int dj = dj0; dj < KS; dj++) {
            const float* q = g_sad + (size_t)(mdi*25 + dj) * NPIX + (size_t)qrow * WW + (x + 12 - dj);
            float kxv = wkx[mdi*25 + dj];
            float kyv = wky[mdi*25 + dj];
            #pragma unroll
            for (int p = 0; p < 4; p++) {
                float sad = q[p];
                gx[p] = fmaf(sad, -kxv, gx[p]);
                gy[p] = fmaf(sad, -kyv, gy[p]);
            }
        }
    }

    if (valid) {
        float4 e;
        e.x = fabsf(gx[0]) + fabsf(gy[0]);
        e.y = fabsf(gx[1]) + fabsf(gy[1]);
        e.z = fabsf(gx[2]) + fabsf(gy[2]);
        e.w = fabsf(gx[3]) + fabsf(gy[3]);
        *reinterpret_cast<float4*>(out + (size_t)r * WW + x) = e;
        float m = fmaxf(fmaxf(e.x, e.y), fmaxf(e.z, e.w));
        atomicMax(&blkmax, __float_as_uint(m));
    }
    __syncthreads();
    if (t == 0) atomicMax(&g_max_u, blkmax);
}

// ---------------- K5: normalize + zero border ----------------
__global__ void k_final(float* __restrict__ out) {
    int idx = blockIdx.x * blockDim.x + threadIdx.x;
    if (idx >= NPIX) return;
    int h = idx / WW;
    int ww = idx - h * WW;
    float m = __uint_as_float(g_max_u);
    if (h >= 12 && h < 388 && ww >= 12 && ww < 388) {
        out[idx] = out[idx] / m;
    } else {
        out[idx] = 0.0f;
    }
}

// ---------------- launch ----------------
extern "C" void kernel_launch(void* const* d_in, const int* in_sizes, int n_in,
                              void* d_out, int out_size) {
    const float* cube = (const float*)d_in[0];
    float* out = (float*)d_out;

    k_transpose<<<NPIX / 32, 256>>>(cube);
    k_norm<<<(NPIX + 7) / 8, 256>>>(cube);
    {
        dim3 gA(4, 49);
        k_phaseA<<<gA, 256>>>();
    }
    {
        dim3 gB(3, 47);
        k_phaseB<<<gB, 256>>>(out);
    }
    k_final<<<(NPIX + 255) / 256, 256>>>(out);
}

// round 17
// speedup vs baseline: 1.3462x; 1.3462x over previous
#include <cuda_runtime.h>
#include <cstdint>

#define HH 400
#define WW 400
#define CC 128
#define KS 25
#define NPIX (HH*WW)
#define PW 424                   // padded row stride
#define PROW (HH*PW)             // 169600 floats per channel plane
#define NFLAT (388*PW)           // phase-A center domain (rows 0..387) = 164512
#define SHIFT 16                 // front guard for f-12 window reads

// ---------------- device scratch ----------------
__device__ float g_cubeP[(size_t)CC * PROW + 8192];   // [c][row][424] at +SHIFT; pads zero
__device__ float g_normP[PROW + 8192];                // padded norms at +SHIFT; pads zero
__device__ float g_sad[(size_t)325 * PROW];           // sad planes [mdi*25+dj][padded flat]
__device__ unsigned int g_max_u;

// ---------------- helpers ----------------
__device__ __forceinline__ float kweight(int i, int j) {
    int ii = min(i, 24 - i);
    if (j < 12) return (float)(j - 12 - ii);
    if (j > 12) return (float)(j - 12 + ii);
    return 0.0f;
}
__device__ __forceinline__ float acos_poly(float x) {
    float ax = fabsf(x);
    float p = fmaf(ax, -0.0012624911f, 0.0066700901f);
    p = fmaf(p, ax, -0.0170881256f);
    p = fmaf(p, ax,  0.0308918810f);
    p = fmaf(p, ax, -0.0501743046f);
    p = fmaf(p, ax,  0.0889789874f);
    p = fmaf(p, ax, -0.2145988016f);
    p = fmaf(p, ax,  1.5707963050f);
    float om = 1.0f - ax;
    float s;
    asm("sqrt.approx.f32 %0, %1;" : "=f"(s) : "f"(om));
    float t = s * p;
    return (x < 0.0f) ? (3.14159265358979f - t) : t;
}

// ---------------- K1: transpose pixel-major -> padded channel-major ----------------
__global__ void k_transpose(const float* __restrict__ cube) {
    __shared__ float tile[32][CC + 4];
    int px0 = blockIdx.x * 32;
    int t = threadIdx.x;
    {
        int lp = t >> 3;
        int cbk = (t & 7) << 4;
        const float4* src = reinterpret_cast<const float4*>(cube + (size_t)(px0 + lp) * CC + cbk);
        #pragma unroll
        for (int q = 0; q < 4; q++) {
            float4 v = src[q];
            tile[lp][cbk + 4*q + 0] = v.x;
            tile[lp][cbk + 4*q + 1] = v.y;
            tile[lp][cbk + 4*q + 2] = v.z;
            tile[lp][cbk + 4*q + 3] = v.w;
        }
    }
    __syncthreads();
    int lane = t & 31;
    int crow = t >> 5;
    int px = px0 + lane;
    int row = px / WW;
    int col = px - row * WW;
    size_t dst = SHIFT + (size_t)row * PW + 12 + col;
    #pragma unroll
    for (int it = 0; it < 16; it++) {
        int c = it * 8 + crow;
        g_cubeP[(size_t)c * PROW + dst] = tile[lane][c];
    }
    if (blockIdx.x == 0 && t == 0) g_max_u = 0u;
}

// ---------------- K2: per-pixel norms (warp per pixel) ----------------
__global__ void k_norm(const float* __restrict__ cube) {
    int px = blockIdx.x * 8 + (threadIdx.x >> 5);
    int l = threadIdx.x & 31;
    if (px >= NPIX) return;
    const float* p = cube + (size_t)px * CC;
    float s = 0.0f;
    #pragma unroll
    for (int i = 0; i < 4; i++) { float v = p[l + 32*i]; s = fmaf(v, v, s); }
    #pragma unroll
    for (int o = 16; o; o >>= 1) s += __shfl_xor_sync(0xffffffffu, s, o);
    if (l == 0) {
        int row = px / WW;
        int col = px - row * WW;
        g_normP[SHIFT + (size_t)row * PW + 12 + col] = sqrtf(s);
    }
}

// ---------------- Phase A body (templated on first dj) ----------------
// center pixels = 4 consecutive padded-flat positions f..f+3; shift v=(mdi, dj-12).
// sad plane [mdi*25+dj][f+p] = sad(center f+p, center f+p+v).
template<int DJ0>
__device__ __forceinline__ void phaseA_body(int mdi, int f) {
    const float* cb = g_cubeP + SHIFT + f;
    const float* wb = g_cubeP + SHIFT + f + mdi * PW - 12;   // s[j] at wb + j
    constexpr int K0 = DJ0 >> 2;                              // first float4 chunk index
    constexpr int ND = 25 - DJ0;

    float acc[4][ND];
    #pragma unroll
    for (int p = 0; p < 4; p++)
        #pragma unroll
        for (int d = 0; d < ND; d++) acc[p][d] = 0.0f;

    #pragma unroll 2
    for (int c = 0; c < CC; c++) {
        size_t co = (size_t)c * PROW;
        float4 ct4 = *reinterpret_cast<const float4*>(cb + co);
        float ctv[4] = {ct4.x, ct4.y, ct4.z, ct4.w};
        float s[28];
        #pragma unroll
        for (int k = K0; k < 7; k++) {
            float4 v = *reinterpret_cast<const float4*>(wb + co + 4*k);
            s[4*k + 0] = v.x; s[4*k + 1] = v.y; s[4*k + 2] = v.z; s[4*k + 3] = v.w;
        }
        #pragma unroll
        for (int dj = DJ0; dj < 25; dj++)
            #pragma unroll
            for (int p = 0; p < 4; p++)
                acc[p][dj - DJ0] = fmaf(ctv[p], s[p + dj], acc[p][dj - DJ0]);
    }

    // epilogue: ratio -> acos -> streaming store
    float4 nc4 = *reinterpret_cast<const float4*>(g_normP + SHIFT + f);
    float ncv[4] = {nc4.x, nc4.y, nc4.z, nc4.w};
    float ns[28];
    {
        const float* nb = g_normP + SHIFT + f + mdi * PW - 12;
        #pragma unroll
        for (int k = K0; k < 7; k++) {
            float4 v = *reinterpret_cast<const float4*>(nb + 4*k);
            ns[4*k + 0] = v.x; ns[4*k + 1] = v.y; ns[4*k + 2] = v.z; ns[4*k + 3] = v.w;
        }
    }
    #pragma unroll
    for (int dj = DJ0; dj < 25; dj++) {
        float4 sad4;
        float* sp = &sad4.x;
        #pragma unroll
        for (int p = 0; p < 4; p++) {
            float den = fmaf(ncv[p], ns[p + dj], 1e-4f);
            float ratio = __fdividef(acc[p][dj - DJ0], den);
            ratio = fminf(fmaxf(ratio, -1.0f + 1e-6f), 1.0f - 1e-6f);
            sp[p] = acos_poly(ratio);
        }
        __stcs(reinterpret_cast<float4*>(g_sad + (size_t)(mdi*25 + dj) * PROW + f), sad4);
    }
}

// grid (161, 13), 256 thr; warp = 128 padded-flat centers, blockIdx.y = mdi.
__global__ void __launch_bounds__(256, 1) k_A() {
    int mdi = blockIdx.y;
    int f = blockIdx.x * 1024 + (threadIdx.x >> 5) * 128 + (threadIdx.x & 31) * 4;
    if (mdi == 0) phaseA_body<13>(0, f);
    else          phaseA_body<0>(mdi, f);
}

// ---------------- Phase B: full weighted gather ----------------
// gx(p) = sum_{v in lower} kx[v] * (plane_v[p] - plane_v[p-v]);   edge = |gx|+|gy|
// grid (3, 94), 128 thr; warp = interior row, lane = 4 cols.
__global__ void __launch_bounds__(128, 4) k_B(float* __restrict__ out) {
    __shared__ unsigned int blkmax;
    if (threadIdx.x == 0) blkmax = 0u;
    __syncthreads();

    const int w = threadIdx.x >> 5;
    const int L = threadIdx.x & 31;
    const int r = 12 + blockIdx.y * 4 + w;           // 12..387
    const int x = 12 + blockIdx.x * 128 + 4 * L;     // 12..392
    const bool valid = (x + 3) <= 387;
    const size_t fp = (size_t)r * PW + 12 + x;       // padded flat (no SHIFT for sad planes)

    float gx[4] = {0,0,0,0};
    float gy[4] = {0,0,0,0};

    #pragma unroll 1
    for (int mdi = 0; mdi < 13; mdi++) {
        int dj0 = (mdi == 0) ? 13 : 0;
        size_t upbase = fp - (size_t)mdi * PW + 12;
        #pragma unroll 5
        for (int dj = dj0; dj < 25; dj++) {
            const float* pl = g_sad + (size_t)(mdi*25 + dj) * PROW;
            float4 lo = *reinterpret_cast<const float4*>(pl + fp);
            const float* up = pl + (upbase - dj);
            float kx = kweight(12 + mdi, dj);
            float ky = kweight(dj, 12 + mdi);
            float d0 = lo.x - up[0];
            float d1 = lo.y - up[1];
            float d2 = lo.z - up[2];
            float d3 = lo.w - up[3];
            gx[0] = fmaf(d0, kx, gx[0]);  gy[0] = fmaf(d0, ky, gy[0]);
            gx[1] = fmaf(d1, kx, gx[1]);  gy[1] = fmaf(d1, ky, gy[1]);
            gx[2] = fmaf(d2, kx, gx[2]);  gy[2] = fmaf(d2, ky, gy[2]);
            gx[3] = fmaf(d3, kx, gx[3]);  gy[3] = fmaf(d3, ky, gy[3]);
        }
    }

    if (valid) {
        float4 e;
        e.x = fabsf(gx[0]) + fabsf(gy[0]);
        e.y = fabsf(gx[1]) + fabsf(gy[1]);
        e.z = fabsf(gx[2]) + fabsf(gy[2]);
        e.w = fabsf(gx[3]) + fabsf(gy[3]);
        *reinterpret_cast<float4*>(out + (size_t)r * WW + x) = e;
        float m = fmaxf(fmaxf(e.x, e.y), fmaxf(e.z, e.w));
        atomicMax(&blkmax, __float_as_uint(m));
    }
    __syncthreads();
    if (threadIdx.x == 0) atomicMax(&g_max_u, blkmax);
}

// ---------------- K5: normalize + zero border ----------------
__global__ void k_final(float* __restrict__ out) {
    int idx = blockIdx.x * blockDim.x + threadIdx.x;
    if (idx >= NPIX) return;
    int h = idx / WW;
    int ww = idx - h * WW;
    float m = __uint_as_float(g_max_u);
    if (h >= 12 && h < 388 && ww >= 12 && ww < 388) {
        out[idx] = out[idx] / m;
    } else {
        out[idx] = 0.0f;
    }
}

// ---------------- launch ----------------
extern "C" void kernel_launch(void* const* d_in, const int* in_sizes, int n_in,
                              void* d_out, int out_size) {
    const float* cube = (const float*)d_in[0];
    float* out = (float*)d_out;

    k_transpose<<<NPIX / 32, 256>>>(cube);
    k_norm<<<(NPIX + 7) / 8, 256>>>(cube);
    {
        dim3 gA(161, 13);     // 161 flat tiles x 13 row-offsets
        k_A<<<gA, 256>>>();
    }
    {
        dim3 gB(3, 94);       // 376 interior rows / 4 per CTA
        k_B<<<gB, 128>>>(out);
    }
    k_final<<<(NPIX + 255) / 256, 256>>>(out);
}